// round 15
// baseline (speedup 1.0000x reference)
#include <cuda_runtime.h>
#include <cuda_bf16.h>
#include <cstdint>

// Problem constants (match reference)
#define N_NODES  100000
#define N_EDGES  1600000
#define N_GRAPHS 64

#define SCAN_CH   256
#define SCAN_NB   ((N_NODES + SCAN_CH - 1) / SCAN_CH)   // 391

// ---------------- static device scratch (no allocations allowed) ----------------
__device__ uint2  g_hb [(size_t)N_NODES * 32];   // [N,128] bf16 GEMM output (4 ch / uint2)
__device__ float4 g_x  [(size_t)N_NODES * 32];   // [N,128] fp32 layer output (next input)
__device__ float  g_dinv[N_NODES];
__device__ int    g_deg [N_NODES];
__device__ int    g_off [N_NODES + 1];           // CSR row offsets (by dst)
__device__ int    g_cur [N_NODES];               // placement cursors
__device__ int2   g_edges[N_EDGES];              // {src, norm-bits} sorted by dst
__device__ int    g_part [SCAN_NB];
__device__ int    g_partpre[SCAN_NB];
__device__ float4 g_pool[N_GRAPHS * 32];
__device__ int    g_cnti[N_GRAPHS];

// ---------------- init / degree ----------------
__global__ void init_misc_kernel() {
    int i = blockIdx.x * blockDim.x + threadIdx.x;
    if (i < N_NODES) g_deg[i] = 0;
    if (i < N_GRAPHS * 32) g_pool[i] = make_float4(0.f, 0.f, 0.f, 0.f);
    if (i < N_GRAPHS) g_cnti[i] = 0;
}

// edge_index is int32 on device (JAX x64 disabled: jnp.int64 -> int32).
__global__ void deg_kernel(const int* __restrict__ ei) {
    int stride = gridDim.x * blockDim.x;
    for (int e = blockIdx.x * blockDim.x + threadIdx.x; e < N_EDGES; e += stride) {
        atomicAdd(&g_deg[ei[N_EDGES + e]], 1);
    }
}

// per-graph node counts (batch sorted -> mostly-uniform warps -> REDUX aggregation)
__global__ void cnt_kernel(const int* __restrict__ batch) {
    int i = blockIdx.x * blockDim.x + threadIdx.x;
    if (i < N_NODES) atomicAdd(&g_cnti[batch[i]], 1);
}

// ---------------- 3-phase grid-wide exclusive scan of g_deg ----------------
__global__ __launch_bounds__(SCAN_CH) void part_kernel() {
    __shared__ int sh[SCAN_CH];
    int i = blockIdx.x * SCAN_CH + threadIdx.x;
    sh[threadIdx.x] = (i < N_NODES) ? g_deg[i] : 0;
    __syncthreads();
    for (int off = SCAN_CH / 2; off > 0; off >>= 1) {
        if (threadIdx.x < off) sh[threadIdx.x] += sh[threadIdx.x + off];
        __syncthreads();
    }
    if (threadIdx.x == 0) g_part[blockIdx.x] = sh[0];
}

__global__ __launch_bounds__(512) void scan_part_kernel() {
    __shared__ int sh[512];
    int t = threadIdx.x;
    sh[t] = (t < SCAN_NB) ? g_part[t] : 0;
    __syncthreads();
    for (int off = 1; off < 512; off <<= 1) {
        int v = (t >= off) ? sh[t - off] : 0;
        __syncthreads();
        sh[t] += v;
        __syncthreads();
    }
    if (t < SCAN_NB) g_partpre[t] = (t == 0) ? 0 : sh[t - 1];
}

__global__ __launch_bounds__(SCAN_CH) void offsets_kernel() {
    __shared__ int sh[SCAN_CH];
    int t = threadIdx.x;
    int i = blockIdx.x * SCAN_CH + t;
    int d = (i < N_NODES) ? g_deg[i] : 0;
    sh[t] = d;
    __syncthreads();
    for (int off = 1; off < SCAN_CH; off <<= 1) {
        int v = (t >= off) ? sh[t - off] : 0;
        __syncthreads();
        sh[t] += v;
        __syncthreads();
    }
    if (i < N_NODES) {
        int off = g_partpre[blockIdx.x] + sh[t] - d;   // exclusive
        g_off[i] = off;
        g_cur[i] = off;
        g_dinv[i] = rsqrtf((float)(d + 1));            // +1 self-loop
        if (i == N_NODES - 1) g_off[N_NODES] = N_EDGES;
    }
}

// ---------------- CSR placement: edges bucketed by dst, norm precomputed ----------------
__global__ void place_kernel(const int* __restrict__ ei) {
    int stride = gridDim.x * blockDim.x;
    for (int e = blockIdx.x * blockDim.x + threadIdx.x; e < N_EDGES; e += stride) {
        int s = ei[e];
        int d = ei[N_EDGES + e];
        int pos = atomicAdd(&g_cur[d], 1);
        float nrm = g_dinv[s] * g_dinv[d];
        g_edges[pos] = make_int2(s, __float_as_int(nrm));
    }
}

// ---------------- GEMM: g_hb = bf16(in[N,128] @ W[128,128]) (fp32 accumulate) ----------------
__global__ __launch_bounds__(256) void gemm_kernel(const float* __restrict__ in,
                                                   const float* __restrict__ W) {
    __shared__ float ws[64][128];
    __shared__ float xs[64][64];
    const int t  = threadIdx.x;
    const int tx = t & 31;
    const int ty = t >> 5;
    const int row0 = blockIdx.x * 64;

    float acc[8][4];
#pragma unroll
    for (int i = 0; i < 8; i++)
#pragma unroll
        for (int j = 0; j < 4; j++) acc[i][j] = 0.f;

    for (int k0 = 0; k0 < 128; k0 += 64) {
        const float4* Wg = (const float4*)(W + (size_t)k0 * 128);
#pragma unroll
        for (int j = 0; j < 8; j++) {
            int idx = j * 256 + t;
            ((float4*)ws)[idx] = Wg[idx];
        }
#pragma unroll
        for (int j = 0; j < 4; j++) {
            int idx = j * 256 + t;
            int r   = idx >> 4;
            int c4  = idx & 15;
            int row = row0 + r;
            float4 v = make_float4(0.f, 0.f, 0.f, 0.f);
            if (row < N_NODES) v = *(const float4*)(in + (size_t)row * 128 + k0 + c4 * 4);
            *(float4*)&xs[r][c4 * 4] = v;
        }
        __syncthreads();
#pragma unroll 8
        for (int kk = 0; kk < 64; kk++) {
            float4 w = *(const float4*)&ws[kk][tx * 4];
#pragma unroll
            for (int i = 0; i < 8; i++) {
                float xv = xs[ty * 8 + i][kk];
                acc[i][0] = fmaf(xv, w.x, acc[i][0]);
                acc[i][1] = fmaf(xv, w.y, acc[i][1]);
                acc[i][2] = fmaf(xv, w.z, acc[i][2]);
                acc[i][3] = fmaf(xv, w.w, acc[i][3]);
            }
        }
        __syncthreads();
    }
#pragma unroll
    for (int i = 0; i < 8; i++) {
        int row = row0 + ty * 8 + i;
        if (row < N_NODES) {
            __nv_bfloat162 p0 = __floats2bfloat162_rn(acc[i][0], acc[i][1]);
            __nv_bfloat162 p1 = __floats2bfloat162_rn(acc[i][2], acc[i][3]);
            uint2 u;
            u.x = *(unsigned int*)&p0;
            u.y = *(unsigned int*)&p1;
            g_hb[(size_t)row * 32 + tx] = u;
        }
    }
}

// ---------------- gather core: acc = dinv^2*h[n] + sum nrm*h[src] (bf16 h) ----------------
__device__ __forceinline__ float4 gather_acc(int n, int lane) {
    float d2 = g_dinv[n];
    d2 = d2 * d2;
    uint2 u0 = g_hb[(size_t)n * 32 + lane];
    float2 a0 = __bfloat1622float2(*(__nv_bfloat162*)&u0.x);
    float2 a1 = __bfloat1622float2(*(__nv_bfloat162*)&u0.y);
    float4 acc = make_float4(d2 * a0.x, d2 * a0.y, d2 * a1.x, d2 * a1.y);

    const int beg = g_off[n];
    const int end = g_off[n + 1];

    int e = beg;
    // unroll-4 for memory-level parallelism on the random h gathers
    for (; e + 3 < end; e += 4) {
        int2 e0 = g_edges[e];
        int2 e1 = g_edges[e + 1];
        int2 e2 = g_edges[e + 2];
        int2 e3 = g_edges[e + 3];
        uint2 v0 = g_hb[(size_t)e0.x * 32 + lane];
        uint2 v1 = g_hb[(size_t)e1.x * 32 + lane];
        uint2 v2 = g_hb[(size_t)e2.x * 32 + lane];
        uint2 v3 = g_hb[(size_t)e3.x * 32 + lane];
        float n0 = __int_as_float(e0.y), n1 = __int_as_float(e1.y);
        float n2 = __int_as_float(e2.y), n3 = __int_as_float(e3.y);
        float2 f;
        f = __bfloat1622float2(*(__nv_bfloat162*)&v0.x); acc.x = fmaf(n0, f.x, acc.x); acc.y = fmaf(n0, f.y, acc.y);
        f = __bfloat1622float2(*(__nv_bfloat162*)&v0.y); acc.z = fmaf(n0, f.x, acc.z); acc.w = fmaf(n0, f.y, acc.w);
        f = __bfloat1622float2(*(__nv_bfloat162*)&v1.x); acc.x = fmaf(n1, f.x, acc.x); acc.y = fmaf(n1, f.y, acc.y);
        f = __bfloat1622float2(*(__nv_bfloat162*)&v1.y); acc.z = fmaf(n1, f.x, acc.z); acc.w = fmaf(n1, f.y, acc.w);
        f = __bfloat1622float2(*(__nv_bfloat162*)&v2.x); acc.x = fmaf(n2, f.x, acc.x); acc.y = fmaf(n2, f.y, acc.y);
        f = __bfloat1622float2(*(__nv_bfloat162*)&v2.y); acc.z = fmaf(n2, f.x, acc.z); acc.w = fmaf(n2, f.y, acc.w);
        f = __bfloat1622float2(*(__nv_bfloat162*)&v3.x); acc.x = fmaf(n3, f.x, acc.x); acc.y = fmaf(n3, f.y, acc.y);
        f = __bfloat1622float2(*(__nv_bfloat162*)&v3.y); acc.z = fmaf(n3, f.x, acc.z); acc.w = fmaf(n3, f.y, acc.w);
    }
    for (; e < end; e++) {
        int2 e0 = g_edges[e];
        uint2 v0 = g_hb[(size_t)e0.x * 32 + lane];
        float n0 = __int_as_float(e0.y);
        float2 f;
        f = __bfloat1622float2(*(__nv_bfloat162*)&v0.x); acc.x = fmaf(n0, f.x, acc.x); acc.y = fmaf(n0, f.y, acc.y);
        f = __bfloat1622float2(*(__nv_bfloat162*)&v0.y); acc.z = fmaf(n0, f.x, acc.z); acc.w = fmaf(n0, f.y, acc.w);
    }
    return acc;
}

// layers 0,1: write relu(acc+b) to g_x (next GEMM input)
__global__ __launch_bounds__(256) void gather_kernel(const float* __restrict__ b) {
    const int lane = threadIdx.x & 31;
    const int n    = (blockIdx.x * blockDim.x + threadIdx.x) >> 5;
    if (n >= N_NODES) return;
    const float4 bb = *(const float4*)(b + lane * 4);
    float4 acc = gather_acc(n, lane);
    float4 o;
    o.x = fmaxf(acc.x + bb.x, 0.f);
    o.y = fmaxf(acc.y + bb.y, 0.f);
    o.z = fmaxf(acc.z + bb.z, 0.f);
    o.w = fmaxf(acc.w + bb.w, 0.f);
    g_x[(size_t)n * 32 + lane] = o;
}

// layer 2: fuse mean-pool — RED relu(acc+b) straight into g_pool[batch[n]]
__global__ __launch_bounds__(256) void gather_pool_kernel(const float* __restrict__ b,
                                                          const int* __restrict__ batch) {
    const int lane = threadIdx.x & 31;
    const int n    = (blockIdx.x * blockDim.x + threadIdx.x) >> 5;
    if (n >= N_NODES) return;
    const float4 bb = *(const float4*)(b + lane * 4);
    float4 acc = gather_acc(n, lane);
    float ox = fmaxf(acc.x + bb.x, 0.f);
    float oy = fmaxf(acc.y + bb.y, 0.f);
    float oz = fmaxf(acc.z + bb.z, 0.f);
    float ow = fmaxf(acc.w + bb.w, 0.f);
    float4* p = &g_pool[batch[n] * 32 + lane];
    asm volatile("red.global.add.v4.f32 [%0], {%1, %2, %3, %4};"
                 :: "l"(p), "f"(ox), "f"(oy), "f"(oz), "f"(ow)
                 : "memory");
}

// ---------------- final: out[g,o] = (pool_sum[g] . Wlin[:,o]) / cnt[g] + blin[o] ----------------
__global__ void final_kernel(const float* __restrict__ Wlin,
                             const float* __restrict__ blin,
                             float* __restrict__ out) {
    __shared__ float ps[128];
    int g = blockIdx.x;
    int o = threadIdx.x;   // 64 threads
    for (int i = o; i < 128; i += 64) ps[i] = ((const float*)g_pool)[g * 128 + i];
    __syncthreads();
    float inv_cnt = 1.0f / fmaxf((float)g_cnti[g], 1.0f);
    float s = 0.f;
#pragma unroll 8
    for (int k = 0; k < 128; k++) s = fmaf(ps[k], Wlin[k * 64 + o], s);
    out[g * 64 + o] = s * inv_cnt + blin[o];
}

// ---------------- launcher ----------------
extern "C" void kernel_launch(void* const* d_in, const int* in_sizes, int n_in,
                              void* d_out, int out_size) {
    const float* x     = (const float*)d_in[0];
    const int*   ei    = (const int*)d_in[1];     // int32 (JAX x64 disabled)
    const int*   batch = (const int*)d_in[2];     // int32
    const float* W1    = (const float*)d_in[3];
    const float* b1    = (const float*)d_in[4];
    const float* W2    = (const float*)d_in[5];
    const float* b2    = (const float*)d_in[6];
    const float* W3    = (const float*)d_in[7];
    const float* b3    = (const float*)d_in[8];
    const float* Wlin  = (const float*)d_in[9];
    const float* blin  = (const float*)d_in[10];
    float* out = (float*)d_out;

    // One-time setup on the uncaptured correctness call: symbol address,
    // side stream + fork/join events (no device allocations).
    static const float* gx_ptr = nullptr;
    static cudaStream_t sB;
    static cudaEvent_t  evFork, evJoin;
    if (!gx_ptr) {
        void* p = nullptr;
        cudaGetSymbolAddress(&p, g_x);
        gx_ptr = (const float*)p;
        cudaStreamCreateWithFlags(&sB, cudaStreamNonBlocking);
        cudaEventCreateWithFlags(&evFork, cudaEventDisableTiming);
        cudaEventCreateWithFlags(&evJoin, cudaEventDisableTiming);
    }

    const int node_blocks   = (N_NODES + 255) / 256;          // 391
    const int gemm_blocks   = (N_NODES + 63) / 64;            // 1563
    const int gather_blocks = (N_NODES * 32 + 255) / 256;     // 12500 (1 warp/node)

    // Fork: CSR build + counts on stream B, overlapped with GEMM-1 on stream 0.
    cudaEventRecord(evFork, 0);
    cudaStreamWaitEvent(sB, evFork, 0);

    init_misc_kernel<<<node_blocks, 256, 0, sB>>>();
    deg_kernel<<<1024, 256, 0, sB>>>(ei);
    cnt_kernel<<<node_blocks, 256, 0, sB>>>(batch);
    part_kernel<<<SCAN_NB, SCAN_CH, 0, sB>>>();
    scan_part_kernel<<<1, 512, 0, sB>>>();
    offsets_kernel<<<SCAN_NB, SCAN_CH, 0, sB>>>();
    place_kernel<<<1024, 256, 0, sB>>>(ei);
    cudaEventRecord(evJoin, sB);

    // GEMM-1 runs concurrently with the CSR build.
    gemm_kernel<<<gemm_blocks, 256>>>(x, W1);

    // Join before first gather (needs g_off/g_edges/g_dinv).
    cudaStreamWaitEvent(0, evJoin, 0);
    gather_kernel<<<gather_blocks, 256>>>(b1);

    gemm_kernel<<<gemm_blocks, 256>>>(gx_ptr, W2);
    gather_kernel<<<gather_blocks, 256>>>(b2);

    gemm_kernel<<<gemm_blocks, 256>>>(gx_ptr, W3);
    gather_pool_kernel<<<gather_blocks, 256>>>(b3, batch);

    final_kernel<<<N_GRAPHS, 64>>>(Wlin, blin, out);
}